// round 11
// baseline (speedup 1.0000x reference)
#include <cuda_runtime.h>
#include <cuda_bf16.h>
#include <cuda_fp16.h>
#include <cstdint>

#define NB 8
#define NN 4096
#define NM 1024
#define ND 256

// ---------------- scratch (device globals; no runtime allocation) ----------------
static constexpr size_t OFF_WHT = 0;
static constexpr size_t OFF_WLT = OFF_WHT + (size_t)ND * ND;
static constexpr size_t OFF_WGT = OFF_WLT + (size_t)ND * ND;
static constexpr size_t OFF_BLG = OFF_WGT + (size_t)ND * ND;
static constexpr size_t OFF_HHI = OFF_BLG + 512;                       // u32 bf16 pairs
static constexpr size_t OFF_HLO = OFF_HHI + (size_t)NB * NN * ND / 2;
static constexpr size_t OFF_LHI = OFF_HLO + (size_t)NB * NN * ND / 2;
static constexpr size_t OFF_LLO = OFF_LHI + (size_t)NB * NM * ND / 2;
static constexpr size_t OFF_G   = OFF_LLO + (size_t)NB * NM * ND / 2;  // fp32
static constexpr size_t OFF_GT  = OFF_G   + (size_t)NB * NM * ND;      // fp16 [B,D,M]
static constexpr size_t SCRATCH_TOTAL = OFF_GT + (size_t)NB * ND * NM / 2;

__device__ float g_scratch[SCRATCH_TOTAL];

// ---------------- helpers ----------------
__device__ __forceinline__ uint32_t f2tf(float x) {
    uint32_t r;
    asm("cvt.rna.tf32.f32 %0, %1;" : "=r"(r) : "f"(x));
    return r;
}
__device__ __forceinline__ uint32_t pack_bf(float x, float y) {
    __nv_bfloat162 t = __floats2bfloat162_rn(x, y);
    return *(uint32_t*)&t;
}
__device__ __forceinline__ uint32_t pack_hf(float x, float y) {
    __half2 t = __floats2half2_rn(x, y);
    return *(uint32_t*)&t;
}
__device__ __forceinline__ float bf_res(float x) {
    return x - __bfloat162float(__float2bfloat16_rn(x));
}
__device__ __forceinline__ void cp16(uint32_t dst, const void* src) {
    asm volatile("cp.async.cg.shared.global [%0], [%1], 16;" :: "r"(dst), "l"(src));
}
__device__ __forceinline__ void ldsm_x4(uint32_t& r0, uint32_t& r1, uint32_t& r2,
                                        uint32_t& r3, uint32_t addr) {
    asm volatile("ldmatrix.sync.aligned.m8n8.x4.shared.b16 {%0,%1,%2,%3}, [%4];"
                 : "=r"(r0), "=r"(r1), "=r"(r2), "=r"(r3) : "r"(addr));
}

#define MMA8(d, a, b)                                                          \
    asm volatile(                                                              \
        "mma.sync.aligned.m16n8k8.row.col.f32.tf32.tf32.f32 "                  \
        "{%0,%1,%2,%3},{%4,%5,%6,%7},{%8,%9},{%0,%1,%2,%3};\n"                 \
        : "+f"((d)[0]), "+f"((d)[1]), "+f"((d)[2]), "+f"((d)[3])               \
        : "r"((a)[0]), "r"((a)[1]), "r"((a)[2]), "r"((a)[3]),                  \
          "r"((b)[0]), "r"((b)[1]))

#define MMA16B(d, a, b)                                                        \
    asm volatile(                                                              \
        "mma.sync.aligned.m16n8k16.row.col.f32.bf16.bf16.f32 "                 \
        "{%0,%1,%2,%3},{%4,%5,%6,%7},{%8,%9},{%0,%1,%2,%3};\n"                 \
        : "+f"((d)[0]), "+f"((d)[1]), "+f"((d)[2]), "+f"((d)[3])               \
        : "r"((a)[0]), "r"((a)[1]), "r"((a)[2]), "r"((a)[3]),                  \
          "r"((b)[0]), "r"((b)[1]))

#define MMA16H(d, a, b)                                                        \
    asm volatile(                                                              \
        "mma.sync.aligned.m16n8k16.row.col.f32.f16.f16.f32 "                   \
        "{%0,%1,%2,%3},{%4,%5,%6,%7},{%8,%9},{%0,%1,%2,%3};\n"                 \
        : "+f"((d)[0]), "+f"((d)[1]), "+f"((d)[2]), "+f"((d)[3])               \
        : "r"((a)[0]), "r"((a)[1]), "r"((a)[2]), "r"((a)[3]),                  \
          "r"((b)[0]), "r"((b)[1]))

// ---------------- weight transpose + bias concat ----------------
__global__ void transpose_w_k(const float* __restrict__ Wh,
                              const float* __restrict__ Wl,
                              const float* __restrict__ Wg,
                              const float* __restrict__ bl,
                              const float* __restrict__ bg,
                              float* __restrict__ wht,
                              float* __restrict__ wlt,
                              float* __restrict__ wgt,
                              float* __restrict__ blg) {
    int i = blockIdx.x * blockDim.x + threadIdx.x;
    int n = i >> 8, k = i & 255;
    wht[i] = Wh[k * ND + n];
    wlt[i] = Wl[k * ND + n];
    wgt[i] = Wg[k * ND + n];
    if (i < 512) blg[i] = (i < 256) ? bl[i] : bg[i - 256];
}

// ---------------- G transpose -> fp16: GT[b][d][m] ----------------
__global__ void transpose_g_k(const float* __restrict__ G, __half* __restrict__ GT) {
    __shared__ float t[32][33];
    int b = blockIdx.z;
    int m0 = blockIdx.x * 32, d0 = blockIdx.y * 32;
    const float* src = G + (size_t)b * NM * ND;
    __half* dst = GT + (size_t)b * ND * NM;
    int x = threadIdx.x, y = threadIdx.y;
#pragma unroll
    for (int i = 0; i < 32; i += 8) t[y + i][x] = src[(size_t)(m0 + y + i) * ND + d0 + x];
    __syncthreads();
#pragma unroll
    for (int i = 0; i < 32; i += 8)
        dst[(size_t)(d0 + y + i) * NM + m0 + x] = __float2half_rn(t[x][y + i]);
}

// ---------------- split-tf32 TT GEMM with bf16-pair packing epilogue ----------------
template <bool BIAS, int OUT>
__global__ void __launch_bounds__(256)
gemm_tt(const float* __restrict__ Aptr, const float* __restrict__ Bptr,
        const float* __restrict__ bias,
        uint32_t* __restrict__ Chi, uint32_t* __restrict__ Clo,
        float* __restrict__ Cg, int K, int Ncols) {
    constexpr int BM = 128, BN = 128, BK = 32, LDSR = 36;
    extern __shared__ uint32_t smem_u[];
    uint32_t* As = smem_u;
    uint32_t* Bs = smem_u + BM * LDSR;
    uint32_t* Al = smem_u + 2 * BM * LDSR;
    uint32_t* Bl = smem_u + 3 * BM * LDSR;

    int tid = threadIdx.x;
    int lane = tid & 31, wid = tid >> 5;
    int wm = wid >> 1, wn = wid & 1;
    int grp = lane >> 2, tq = lane & 3;

    const float* A = Aptr + (long long)blockIdx.x * BM * K;
    const float* Bm = Bptr + (long long)blockIdx.y * BN * K;

    float acc[2][8][4];
#pragma unroll
    for (int i = 0; i < 2; i++)
#pragma unroll
        for (int j = 0; j < 8; j++)
#pragma unroll
            for (int q = 0; q < 4; q++) acc[i][j][q] = 0.f;

    for (int kc = 0; kc < K; kc += BK) {
        __syncthreads();
#pragma unroll
        for (int it = 0; it < 4; it++) {
            int idx = tid + it * 256;
            int rr = idx >> 3, cc = (idx & 7) * 4;
            float4 va = *(const float4*)(A + (long long)rr * K + kc + cc);
            float4 vb = *(const float4*)(Bm + (long long)rr * K + kc + cc);
            uint32_t* pa = As + rr * LDSR + cc;
            uint32_t* pb = Bs + rr * LDSR + cc;
            uint32_t h;
            h = f2tf(va.x); pa[0] = h; Al[rr * LDSR + cc + 0] = f2tf(va.x - __uint_as_float(h));
            h = f2tf(va.y); pa[1] = h; Al[rr * LDSR + cc + 1] = f2tf(va.y - __uint_as_float(h));
            h = f2tf(va.z); pa[2] = h; Al[rr * LDSR + cc + 2] = f2tf(va.z - __uint_as_float(h));
            h = f2tf(va.w); pa[3] = h; Al[rr * LDSR + cc + 3] = f2tf(va.w - __uint_as_float(h));
            h = f2tf(vb.x); pb[0] = h; Bl[rr * LDSR + cc + 0] = f2tf(vb.x - __uint_as_float(h));
            h = f2tf(vb.y); pb[1] = h; Bl[rr * LDSR + cc + 1] = f2tf(vb.y - __uint_as_float(h));
            h = f2tf(vb.z); pb[2] = h; Bl[rr * LDSR + cc + 2] = f2tf(vb.z - __uint_as_float(h));
            h = f2tf(vb.w); pb[3] = h; Bl[rr * LDSR + cc + 3] = f2tf(vb.w - __uint_as_float(h));
        }
        __syncthreads();
#pragma unroll
        for (int ks = 0; ks < 4; ks++) {
            int k0 = ks * 8;
            uint32_t a[2][4], al[2][4];
            uint32_t b[8][2], bl2[8][2];
#pragma unroll
            for (int i = 0; i < 2; i++) {
                int ro = (wm * 32 + i * 16 + grp) * LDSR + k0 + tq;
                a[i][0] = As[ro];
                a[i][1] = As[ro + 8 * LDSR];
                a[i][2] = As[ro + 4];
                a[i][3] = As[ro + 8 * LDSR + 4];
                al[i][0] = Al[ro];
                al[i][1] = Al[ro + 8 * LDSR];
                al[i][2] = Al[ro + 4];
                al[i][3] = Al[ro + 8 * LDSR + 4];
            }
#pragma unroll
            for (int j = 0; j < 8; j++) {
                int co = (wn * 64 + j * 8 + grp) * LDSR + k0 + tq;
                b[j][0] = Bs[co];
                b[j][1] = Bs[co + 4];
                bl2[j][0] = Bl[co];
                bl2[j][1] = Bl[co + 4];
            }
#pragma unroll
            for (int i = 0; i < 2; i++)
#pragma unroll
                for (int j = 0; j < 8; j++) {
                    MMA8(acc[i][j], al[i], b[j]);
                    MMA8(acc[i][j], a[i], bl2[j]);
                    MMA8(acc[i][j], a[i], b[j]);
                }
        }
    }

    int row0 = blockIdx.x * BM + wm * 32 + grp;
    int col0 = blockIdx.y * BN + wn * 64 + 2 * tq;
#pragma unroll
    for (int i = 0; i < 2; i++) {
#pragma unroll
        for (int j = 0; j < 8; j++) {
            int row = row0 + i * 16;
            int col = col0 + j * 8;
            float2 v0 = make_float2(acc[i][j][0], acc[i][j][1]);
            float2 v1 = make_float2(acc[i][j][2], acc[i][j][3]);
            if (BIAS) {
                float2 bb = *(const float2*)(bias + col);
                v0.x += bb.x; v0.y += bb.y;
                v1.x += bb.x; v1.y += bb.y;
            }
            if (OUT == 1 || (OUT == 2 && col < 256)) {
                int pr = (OUT == 1) ? (Ncols >> 1) : 128;
                long long i0 = (long long)row * pr + (col >> 1);
                long long i1 = (long long)(row + 8) * pr + (col >> 1);
                Chi[i0] = pack_bf(v0.x, v0.y);
                Clo[i0] = pack_bf(bf_res(v0.x), bf_res(v0.y));
                Chi[i1] = pack_bf(v1.x, v1.y);
                Clo[i1] = pack_bf(bf_res(v1.x), bf_res(v1.y));
            } else {
                int gc = col - 256;
                *(float2*)(Cg + (long long)row * 256 + gc) = v0;
                *(float2*)(Cg + (long long)(row + 8) * 256 + gc) = v1;
            }
        }
    }
}

// ---------------- fused scores+softmax+out, 512 threads / 16 warps ----------------
// Phase A: warp (wm 0..7, wn 0..1) = 16 rows x 64 M-cols of scores (bf16x3, ldmatrix).
// Softmax: quad-reduce + smem stats exchange across the 2 col-half warps.
// Attn -> smem fp16 (128x128); Phase C: warp (wm, ch=wn) = 16 rows x 128 out-cols,
// A-frags ldmatrix'd from attn smem, B from resident GT tile; o fp32 across M.
__global__ void __launch_bounds__(512, 1)
fused_attn(const uint32_t* __restrict__ Hhi, const uint32_t* __restrict__ Hlo,
           const uint32_t* __restrict__ Lhi, const uint32_t* __restrict__ Llo,
           const uint32_t* __restrict__ Gt,  // fp16 pairs [B,256,512] u32
           const float* __restrict__ p, float* __restrict__ out) {
    constexpr int LDSR = 20, ARR = 128 * LDSR, STAGE = 4 * ARR;  // u32
    constexpr int LDG = 68;   // sG row stride, u32 (272B: 16B-aligned, ldmatrix conflict-free)
    constexpr int LDP = 68;   // attn row stride, u32
    constexpr int OFF_SG = 2 * STAGE;            // 256 x 68
    constexpr int OFF_SP = OFF_SG + 256 * LDG;   // 128 x 68
    constexpr int OFF_ST = OFF_SP + 128 * LDP;   // stats: 256 m + 256 s floats
    extern __shared__ uint32_t sm[];
    uint32_t sbase = (uint32_t)__cvta_generic_to_shared(sm);
    uint32_t gbase = sbase + OFF_SG * 4;
    uint32_t pbase = sbase + OFF_SP * 4;
    uint32_t* sP = sm + OFF_SP;
    float* stm = (float*)(sm + OFF_ST);
    float* sts = stm + 256;

    int tid = threadIdx.x;
    int lane = tid & 31, wid = tid >> 5;
    int wm = wid >> 1, wn = wid & 1;     // phase A: rows wm*16, cols wn*64; phase C: ch=wn
    int grp = lane >> 2, tq = lane & 3;
    int l15 = lane & 15, l16 = lane >> 4;
    int bx = blockIdx.x, zb = blockIdx.z;

    const uint32_t* Ah = Hhi + ((long long)zb * NN + bx * 128) * 128;
    const uint32_t* Alg = Hlo + ((long long)zb * NN + bx * 128) * 128;
    const uint32_t* Bh_b = Lhi + (long long)zb * NM * 128;
    const uint32_t* Bl_b = Llo + (long long)zb * NM * 128;
    const uint32_t* Gtb = Gt + (long long)zb * 256 * 512;

    // ldmatrix per-lane byte offsets
    uint32_t frA = (uint32_t)((wm * 16 + l15) * LDSR) * 4 + l16 * 16;      // within stage
    uint32_t frB = (uint32_t)((wn * 64 + l15) * LDSR) * 4 + l16 * 16;
    uint32_t frP = pbase + (uint32_t)((wm * 16 + l15) * LDP) * 4 + l16 * 16;
    uint32_t frG = gbase + (uint32_t)((wn * 128 + l15) * LDG) * 4 + l16 * 16;

    // cp.async slots: one float4 per array per thread (512 threads x 4 = 128x16 u32)
    int rr = tid >> 2, uc = (tid & 3) * 4;
    uint32_t cpo = (uint32_t)(rr * LDSR + uc) * 4;

    float o[16][4];
#pragma unroll
    for (int j = 0; j < 16; j++)
#pragma unroll
        for (int q = 0; q < 4; q++) o[j][q] = 0.f;
    float m0 = -1e30f, m1 = -1e30f, s0 = 0.f, s1 = 0.f;

    int r0 = wm * 16 + grp, r1 = r0 + 8;  // CTA-local rows

    for (int mt = 0; mt < 8; mt++) {
        const uint32_t* Bh = Bh_b + (long long)mt * 128 * 128;
        const uint32_t* Bl = Bl_b + (long long)mt * 128 * 128;

        auto issue = [&](int st, int kcp, int ch) {
            uint32_t dA = sbase + (uint32_t)st * STAGE * 4;
            cp16(dA + cpo, Ah + (long long)rr * 128 + kcp + uc);
            cp16(dA + ARR * 4 + cpo, Bh + (long long)rr * 128 + kcp + uc);
            cp16(dA + 2 * ARR * 4 + cpo, Alg + (long long)rr * 128 + kcp + uc);
            cp16(dA + 3 * ARR * 4 + cpo, Bl + (long long)rr * 128 + kcp + uc);
            int g = ch * 512 + tid;            // 4096 float4 over 8 chunks
            int gr = g >> 4, gc = (g & 15) * 4;
            cp16(gbase + (uint32_t)(gr * LDG + gc) * 4, Gtb + (long long)gr * 512 + mt * 64 + gc);
            asm volatile("cp.async.commit_group;");
        };

        float c[8][4];
#pragma unroll
        for (int j = 0; j < 8; j++)
#pragma unroll
            for (int q = 0; q < 4; q++) c[j][q] = 0.f;

        // ---- phase A: scores (cp.async double-buffered, ldmatrix frags) ----
        issue(0, 0, 0);
        asm volatile("cp.async.wait_group 0;");
        __syncthreads();
        for (int t = 0; t < 8; t++) {
            if (t + 1 < 8) issue((t + 1) & 1, (t + 1) * 16, t + 1);
            uint32_t sb = sbase + (uint32_t)(t & 1) * STAGE * 4;
            uint32_t sbA = sb + frA;
            uint32_t sbAl = sb + 2 * ARR * 4 + frA;
            uint32_t sbB = sb + ARR * 4 + frB;
            uint32_t sbBl = sb + 3 * ARR * 4 + frB;
#pragma unroll
            for (int ks = 0; ks < 2; ks++) {
                uint32_t a[4], al[4];
                ldsm_x4(a[0], a[1], a[2], a[3], sbA + ks * 32);
                ldsm_x4(al[0], al[1], al[2], al[3], sbAl + ks * 32);
#pragma unroll
                for (int jj = 0; jj < 4; jj++) {
                    uint32_t h0, h1, h2, h3, g0, g1, g2, g3;
                    ldsm_x4(h0, h1, h2, h3, sbB + jj * 1280 + ks * 32);
                    ldsm_x4(g0, g1, g2, g3, sbBl + jj * 1280 + ks * 32);
                    uint32_t b0[2] = {h0, h2}, b1[2] = {h1, h3};
                    uint32_t e0[2] = {g0, g2}, e1[2] = {g1, g3};
                    MMA16B(c[2 * jj], al, b0);
                    MMA16B(c[2 * jj], a, e0);
                    MMA16B(c[2 * jj], a, b0);
                    MMA16B(c[2 * jj + 1], al, b1);
                    MMA16B(c[2 * jj + 1], a, e1);
                    MMA16B(c[2 * jj + 1], a, b1);
                }
            }
            if (t + 1 < 8) asm volatile("cp.async.wait_group 0;");
            __syncthreads();
        }

        // ---- phase B: online softmax with cross-warp (wn) stats exchange ----
        float mx0 = -1e30f, mx1 = -1e30f;
#pragma unroll
        for (int j = 0; j < 8; j++) {
            mx0 = fmaxf(mx0, fmaxf(c[j][0], c[j][1]));
            mx1 = fmaxf(mx1, fmaxf(c[j][2], c[j][3]));
        }
        mx0 = fmaxf(mx0, __shfl_xor_sync(0xffffffffu, mx0, 1));
        mx0 = fmaxf(mx0, __shfl_xor_sync(0xffffffffu, mx0, 2));
        mx1 = fmaxf(mx1, __shfl_xor_sync(0xffffffffu, mx1, 1));
        mx1 = fmaxf(mx1, __shfl_xor_sync(0xffffffffu, mx1, 2));
        if (tq == 0) {
            stm[r0 * 2 + wn] = mx0;
            stm[r1 * 2 + wn] = mx1;
        }
        __syncthreads();
        float gm0 = fmaxf(stm[r0 * 2], stm[r0 * 2 + 1]);
        float gm1 = fmaxf(stm[r1 * 2], stm[r1 * 2 + 1]);
        float nm0 = fmaxf(m0, gm0), nm1 = fmaxf(m1, gm1);
        float sc0 = __expf(m0 - nm0), sc1 = __expf(m1 - nm1);
        m0 = nm0; m1 = nm1;
        s0 *= sc0; s1 *= sc1;
#pragma unroll
        for (int j = 0; j < 16; j++) {
            o[j][0] *= sc0; o[j][1] *= sc0;
            o[j][2] *= sc1; o[j][3] *= sc1;
        }
        float ps0 = 0.f, ps1 = 0.f;
#pragma unroll
        for (int j = 0; j < 8; j++) {
            c[j][0] = __expf(c[j][0] - m0);
            c[j][1] = __expf(c[j][1] - m0);
            c[j][2] = __expf(c[j][2] - m1);
            c[j][3] = __expf(c[j][3] - m1);
            ps0 += c[j][0] + c[j][1];
            ps1 += c[j][2] + c[j][3];
        }
        ps0 += __shfl_xor_sync(0xffffffffu, ps0, 1);
        ps0 += __shfl_xor_sync(0xffffffffu, ps0, 2);
        ps1 += __shfl_xor_sync(0xffffffffu, ps1, 1);
        ps1 += __shfl_xor_sync(0xffffffffu, ps1, 2);
        if (tq == 0) {
            sts[r0 * 2 + wn] = ps0;
            sts[r1 * 2 + wn] = ps1;
        }
        // pack exp'd attn -> smem fp16 (u32 col = wn*32 + j*4 + tq; conflict-free)
#pragma unroll
        for (int j = 0; j < 8; j++) {
            sP[r0 * LDP + wn * 32 + j * 4 + tq] = pack_hf(c[j][0], c[j][1]);
            sP[r1 * LDP + wn * 32 + j * 4 + tq] = pack_hf(c[j][2], c[j][3]);
        }
        __syncthreads();
        s0 += sts[r0 * 2] + sts[r0 * 2 + 1];
        s1 += sts[r1 * 2] + sts[r1 * 2 + 1];

        // ---- phase C: o += attn @ GT (A from attn smem, B from sG; fp16 MMA) ----
#pragma unroll
        for (int kt = 0; kt < 8; kt++) {
            uint32_t a[4];
            ldsm_x4(a[0], a[1], a[2], a[3], frP + kt * 32);
#pragma unroll
            for (int jj = 0; jj < 8; jj++) {
                uint32_t h0, h1, h2, h3;
                ldsm_x4(h0, h1, h2, h3, frG + jj * (16 * LDG * 4) + kt * 32);
                uint32_t b0[2] = {h0, h2}, b1[2] = {h1, h3};
                MMA16H(o[2 * jj], a, b0);
                MMA16H(o[2 * jj + 1], a, b1);
            }
        }
        __syncthreads();  // stages/sG/attn stable before next tile's copies
    }

    // ---- epilogue: normalize, residual, store ----
    float inv0 = 1.0f / s0, inv1 = 1.0f / s1;
    int grow = bx * 128 + r0;
    float* ob = out + ((long long)zb * NN + grow) * ND;
    const float* pb = p + ((long long)zb * NN + grow) * ND;
#pragma unroll
    for (int j = 0; j < 16; j++) {
        int col = wn * 128 + j * 8 + 2 * tq;
        float2 v0 = make_float2(o[j][0] * inv0 + pb[col], o[j][1] * inv0 + pb[col + 1]);
        float2 v1 = make_float2(o[j][2] * inv1 + pb[8 * ND + col],
                                o[j][3] * inv1 + pb[8 * ND + col + 1]);
        *(float2*)(ob + col) = v0;
        *(float2*)(ob + 8 * ND + col) = v1;
    }
}

// ---------------- launch ----------------
extern "C" void kernel_launch(void* const* d_in, const int* in_sizes, int n_in,
                              void* d_out, int out_size) {
    const float* p  = (const float*)d_in[0];
    const float* r  = (const float*)d_in[1];
    // d_in[2] = batch ids (int64) — unused (implied by layout)
    const float* Wh = (const float*)d_in[3];
    const float* bh = (const float*)d_in[4];
    const float* Wl = (const float*)d_in[5];
    const float* bl = (const float*)d_in[6];
    const float* Wg = (const float*)d_in[7];
    const float* bg = (const float*)d_in[8];
    float* out = (float*)d_out;
    (void)in_sizes; (void)n_in; (void)out_size;

    float* s = nullptr;
    cudaGetSymbolAddress((void**)&s, g_scratch);
    float* WhT = s + OFF_WHT;
    float* WlT = s + OFF_WLT;
    float* BLG = s + OFF_BLG;
    uint32_t* Hhi = (uint32_t*)(s + OFF_HHI);
    uint32_t* Hlo = (uint32_t*)(s + OFF_HLO);
    uint32_t* Lhi = (uint32_t*)(s + OFF_LHI);
    uint32_t* Llo = (uint32_t*)(s + OFF_LLO);
    float* G   = s + OFF_G;
    __half* GTh = (__half*)(s + OFF_GT);

    const int SMEM_TF32 = 4 * 128 * 36 * 4;  // 73728
    // stages 81920 + sG 69632 + attn 34816 + stats 2048
    const int SMEM_FUSED = (2 * 4 * 128 * 20 + 256 * 68 + 128 * 68 + 512) * 4;  // 188416
    cudaFuncSetAttribute(gemm_tt<true, 1>,
                         cudaFuncAttributeMaxDynamicSharedMemorySize, SMEM_TF32);
    cudaFuncSetAttribute(gemm_tt<true, 2>,
                         cudaFuncAttributeMaxDynamicSharedMemorySize, SMEM_TF32);
    cudaFuncSetAttribute(fused_attn,
                         cudaFuncAttributeMaxDynamicSharedMemorySize, SMEM_FUSED);

    // 0. transpose weights; concat biases
    transpose_w_k<<<256, 256>>>(Wh, Wl, Wg, bl, bg, WhT, WlT, WlT + (size_t)ND * ND, BLG);

    // 1. H = p @ Wh + bh  -> packed bf16 hi/lo pairs
    gemm_tt<true, 1><<<dim3(NB * NN / 128, ND / 128, 1), 256, SMEM_TF32>>>(
        p, WhT, bh, Hhi, Hlo, nullptr, ND, ND);

    // 2+3. [L | G] = r @ [Wl | Wg] + [bl | bg]  (L packed bf16, G fp32)
    gemm_tt<true, 2><<<dim3(NB * NM / 128, 2 * ND / 128, 1), 256, SMEM_TF32>>>(
        r, WlT, BLG, Lhi, Llo, G, ND, 2 * ND);

    // 4. GT[b][d][m] fp16
    transpose_g_k<<<dim3(NM / 32, ND / 32, NB), dim3(32, 8)>>>(G, GTh);

    // 5. fused: out = p + softmax(H L^T) @ G   (512 threads, 16 warps)
    fused_attn<<<dim3(NN / 128, 1, NB), 512, SMEM_FUSED>>>(
        Hhi, Hlo, Lhi, Llo, (const uint32_t*)GTh, p, out);
}

// round 12
// speedup vs baseline: 1.0011x; 1.0011x over previous
#include <cuda_runtime.h>
#include <cuda_bf16.h>
#include <cuda_fp16.h>
#include <cstdint>

#define NB 8
#define NN 4096
#define NM 1024
#define ND 256

// ---------------- scratch (device globals; no runtime allocation) ----------------
static constexpr size_t OFF_WHT = 0;
static constexpr size_t OFF_WLT = OFF_WHT + (size_t)ND * ND;
static constexpr size_t OFF_WGT = OFF_WLT + (size_t)ND * ND;
static constexpr size_t OFF_BLG = OFF_WGT + (size_t)ND * ND;
static constexpr size_t OFF_HHI = OFF_BLG + 512;                       // u32 bf16 pairs
static constexpr size_t OFF_HLO = OFF_HHI + (size_t)NB * NN * ND / 2;
static constexpr size_t OFF_LHI = OFF_HLO + (size_t)NB * NN * ND / 2;
static constexpr size_t OFF_LLO = OFF_LHI + (size_t)NB * NM * ND / 2;
static constexpr size_t OFF_G   = OFF_LLO + (size_t)NB * NM * ND / 2;  // fp32
static constexpr size_t OFF_GT  = OFF_G   + (size_t)NB * NM * ND;      // fp16 [B,D,M]
static constexpr size_t SCRATCH_TOTAL = OFF_GT + (size_t)NB * ND * NM / 2;

__device__ float g_scratch[SCRATCH_TOTAL];

// ---------------- helpers ----------------
__device__ __forceinline__ uint32_t f2tf(float x) {
    uint32_t r;
    asm("cvt.rna.tf32.f32 %0, %1;" : "=r"(r) : "f"(x));
    return r;
}
__device__ __forceinline__ uint32_t pack_bf(float x, float y) {
    __nv_bfloat162 t = __floats2bfloat162_rn(x, y);
    return *(uint32_t*)&t;
}
__device__ __forceinline__ uint32_t pack_hf(float x, float y) {
    __half2 t = __floats2half2_rn(x, y);
    return *(uint32_t*)&t;
}
__device__ __forceinline__ float bf_res(float x) {
    return x - __bfloat162float(__float2bfloat16_rn(x));
}
__device__ __forceinline__ void cp16(uint32_t dst, const void* src) {
    asm volatile("cp.async.cg.shared.global [%0], [%1], 16;" :: "r"(dst), "l"(src));
}
__device__ __forceinline__ void ldsm_x4(uint32_t& r0, uint32_t& r1, uint32_t& r2,
                                        uint32_t& r3, uint32_t addr) {
    asm volatile("ldmatrix.sync.aligned.m8n8.x4.shared.b16 {%0,%1,%2,%3}, [%4];"
                 : "=r"(r0), "=r"(r1), "=r"(r2), "=r"(r3) : "r"(addr));
}

#define MMA8(d, a, b)                                                          \
    asm volatile(                                                              \
        "mma.sync.aligned.m16n8k8.row.col.f32.tf32.tf32.f32 "                  \
        "{%0,%1,%2,%3},{%4,%5,%6,%7},{%8,%9},{%0,%1,%2,%3};\n"                 \
        : "+f"((d)[0]), "+f"((d)[1]), "+f"((d)[2]), "+f"((d)[3])               \
        : "r"((a)[0]), "r"((a)[1]), "r"((a)[2]), "r"((a)[3]),                  \
          "r"((b)[0]), "r"((b)[1]))

#define MMA16B(d, a, b)                                                        \
    asm volatile(                                                              \
        "mma.sync.aligned.m16n8k16.row.col.f32.bf16.bf16.f32 "                 \
        "{%0,%1,%2,%3},{%4,%5,%6,%7},{%8,%9},{%0,%1,%2,%3};\n"                 \
        : "+f"((d)[0]), "+f"((d)[1]), "+f"((d)[2]), "+f"((d)[3])               \
        : "r"((a)[0]), "r"((a)[1]), "r"((a)[2]), "r"((a)[3]),                  \
          "r"((b)[0]), "r"((b)[1]))

#define MMA16H(d, a, b)                                                        \
    asm volatile(                                                              \
        "mma.sync.aligned.m16n8k16.row.col.f32.f16.f16.f32 "                   \
        "{%0,%1,%2,%3},{%4,%5,%6,%7},{%8,%9},{%0,%1,%2,%3};\n"                 \
        : "+f"((d)[0]), "+f"((d)[1]), "+f"((d)[2]), "+f"((d)[3])               \
        : "r"((a)[0]), "r"((a)[1]), "r"((a)[2]), "r"((a)[3]),                  \
          "r"((b)[0]), "r"((b)[1]))

// ---------------- weight transpose + bias concat ----------------
__global__ void transpose_w_k(const float* __restrict__ Wh,
                              const float* __restrict__ Wl,
                              const float* __restrict__ Wg,
                              const float* __restrict__ bl,
                              const float* __restrict__ bg,
                              float* __restrict__ wht,
                              float* __restrict__ wlt,
                              float* __restrict__ wgt,
                              float* __restrict__ blg) {
    int i = blockIdx.x * blockDim.x + threadIdx.x;
    int n = i >> 8, k = i & 255;
    wht[i] = Wh[k * ND + n];
    wlt[i] = Wl[k * ND + n];
    wgt[i] = Wg[k * ND + n];
    if (i < 512) blg[i] = (i < 256) ? bl[i] : bg[i - 256];
}

// ---------------- G transpose -> fp16: GT[b][d][m] ----------------
__global__ void transpose_g_k(const float* __restrict__ G, __half* __restrict__ GT) {
    __shared__ float t[32][33];
    int b = blockIdx.z;
    int m0 = blockIdx.x * 32, d0 = blockIdx.y * 32;
    const float* src = G + (size_t)b * NM * ND;
    __half* dst = GT + (size_t)b * ND * NM;
    int x = threadIdx.x, y = threadIdx.y;
#pragma unroll
    for (int i = 0; i < 32; i += 8) t[y + i][x] = src[(size_t)(m0 + y + i) * ND + d0 + x];
    __syncthreads();
#pragma unroll
    for (int i = 0; i < 32; i += 8)
        dst[(size_t)(d0 + y + i) * NM + m0 + x] = __float2half_rn(t[x][y + i]);
}

// ---------------- split-tf32 TT GEMM with bf16-pair packing epilogue ----------------
template <bool BIAS, int OUT>
__global__ void __launch_bounds__(256)
gemm_tt(const float* __restrict__ Aptr, const float* __restrict__ Bptr,
        const float* __restrict__ bias,
        uint32_t* __restrict__ Chi, uint32_t* __restrict__ Clo,
        float* __restrict__ Cg, int K, int Ncols) {
    constexpr int BM = 128, BN = 128, BK = 32, LDSR = 36;
    extern __shared__ uint32_t smem_u[];
    uint32_t* As = smem_u;
    uint32_t* Bs = smem_u + BM * LDSR;
    uint32_t* Al = smem_u + 2 * BM * LDSR;
    uint32_t* Bl = smem_u + 3 * BM * LDSR;

    int tid = threadIdx.x;
    int lane = tid & 31, wid = tid >> 5;
    int wm = wid >> 1, wn = wid & 1;
    int grp = lane >> 2, tq = lane & 3;

    const float* A = Aptr + (long long)blockIdx.x * BM * K;
    const float* Bm = Bptr + (long long)blockIdx.y * BN * K;

    float acc[2][8][4];
#pragma unroll
    for (int i = 0; i < 2; i++)
#pragma unroll
        for (int j = 0; j < 8; j++)
#pragma unroll
            for (int q = 0; q < 4; q++) acc[i][j][q] = 0.f;

    for (int kc = 0; kc < K; kc += BK) {
        __syncthreads();
#pragma unroll
        for (int it = 0; it < 4; it++) {
            int idx = tid + it * 256;
            int rr = idx >> 3, cc = (idx & 7) * 4;
            float4 va = *(const float4*)(A + (long long)rr * K + kc + cc);
            float4 vb = *(const float4*)(Bm + (long long)rr * K + kc + cc);
            uint32_t* pa = As + rr * LDSR + cc;
            uint32_t* pb = Bs + rr * LDSR + cc;
            uint32_t h;
            h = f2tf(va.x); pa[0] = h; Al[rr * LDSR + cc + 0] = f2tf(va.x - __uint_as_float(h));
            h = f2tf(va.y); pa[1] = h; Al[rr * LDSR + cc + 1] = f2tf(va.y - __uint_as_float(h));
            h = f2tf(va.z); pa[2] = h; Al[rr * LDSR + cc + 2] = f2tf(va.z - __uint_as_float(h));
            h = f2tf(va.w); pa[3] = h; Al[rr * LDSR + cc + 3] = f2tf(va.w - __uint_as_float(h));
            h = f2tf(vb.x); pb[0] = h; Bl[rr * LDSR + cc + 0] = f2tf(vb.x - __uint_as_float(h));
            h = f2tf(vb.y); pb[1] = h; Bl[rr * LDSR + cc + 1] = f2tf(vb.y - __uint_as_float(h));
            h = f2tf(vb.z); pb[2] = h; Bl[rr * LDSR + cc + 2] = f2tf(vb.z - __uint_as_float(h));
            h = f2tf(vb.w); pb[3] = h; Bl[rr * LDSR + cc + 3] = f2tf(vb.w - __uint_as_float(h));
        }
        __syncthreads();
#pragma unroll
        for (int ks = 0; ks < 4; ks++) {
            int k0 = ks * 8;
            uint32_t a[2][4], al[2][4];
            uint32_t b[8][2], bl2[8][2];
#pragma unroll
            for (int i = 0; i < 2; i++) {
                int ro = (wm * 32 + i * 16 + grp) * LDSR + k0 + tq;
                a[i][0] = As[ro];
                a[i][1] = As[ro + 8 * LDSR];
                a[i][2] = As[ro + 4];
                a[i][3] = As[ro + 8 * LDSR + 4];
                al[i][0] = Al[ro];
                al[i][1] = Al[ro + 8 * LDSR];
                al[i][2] = Al[ro + 4];
                al[i][3] = Al[ro + 8 * LDSR + 4];
            }
#pragma unroll
            for (int j = 0; j < 8; j++) {
                int co = (wn * 64 + j * 8 + grp) * LDSR + k0 + tq;
                b[j][0] = Bs[co];
                b[j][1] = Bs[co + 4];
                bl2[j][0] = Bl[co];
                bl2[j][1] = Bl[co + 4];
            }
#pragma unroll
            for (int i = 0; i < 2; i++)
#pragma unroll
                for (int j = 0; j < 8; j++) {
                    MMA8(acc[i][j], al[i], b[j]);
                    MMA8(acc[i][j], a[i], bl2[j]);
                    MMA8(acc[i][j], a[i], b[j]);
                }
        }
    }

    int row0 = blockIdx.x * BM + wm * 32 + grp;
    int col0 = blockIdx.y * BN + wn * 64 + 2 * tq;
#pragma unroll
    for (int i = 0; i < 2; i++) {
#pragma unroll
        for (int j = 0; j < 8; j++) {
            int row = row0 + i * 16;
            int col = col0 + j * 8;
            float2 v0 = make_float2(acc[i][j][0], acc[i][j][1]);
            float2 v1 = make_float2(acc[i][j][2], acc[i][j][3]);
            if (BIAS) {
                float2 bb = *(const float2*)(bias + col);
                v0.x += bb.x; v0.y += bb.y;
                v1.x += bb.x; v1.y += bb.y;
            }
            if (OUT == 1 || (OUT == 2 && col < 256)) {
                int pr = (OUT == 1) ? (Ncols >> 1) : 128;
                long long i0 = (long long)row * pr + (col >> 1);
                long long i1 = (long long)(row + 8) * pr + (col >> 1);
                Chi[i0] = pack_bf(v0.x, v0.y);
                Clo[i0] = pack_bf(bf_res(v0.x), bf_res(v0.y));
                Chi[i1] = pack_bf(v1.x, v1.y);
                Clo[i1] = pack_bf(bf_res(v1.x), bf_res(v1.y));
            } else {
                int gc = col - 256;
                *(float2*)(Cg + (long long)row * 256 + gc) = v0;
                *(float2*)(Cg + (long long)(row + 8) * 256 + gc) = v1;
            }
        }
    }
}

// ---------------- fused scores+softmax+out, 512 threads / 16 warps ----------------
// Phase A: warp (wm 0..7, wn 0..1) = 16 rows x 64 M-cols of scores (bf16x3, ldmatrix).
// Softmax: quad-reduce + smem stats exchange across the 2 col-half warps.
// Attn -> smem fp16 (128x128); Phase C: warp (wm, ch=wn) = 16 rows x 128 out-cols,
// A-frags ldmatrix'd from attn smem, B from resident GT tile; o fp32 across M.
__global__ void __launch_bounds__(512, 1)
fused_attn(const uint32_t* __restrict__ Hhi, const uint32_t* __restrict__ Hlo,
           const uint32_t* __restrict__ Lhi, const uint32_t* __restrict__ Llo,
           const uint32_t* __restrict__ Gt,  // fp16 pairs [B,256,512] u32
           const float* __restrict__ p, float* __restrict__ out) {
    constexpr int LDSR = 20, ARR = 128 * LDSR, STAGE = 4 * ARR;  // u32
    constexpr int LDG = 68;   // sG row stride, u32 (272B: 16B-aligned, ldmatrix conflict-free)
    constexpr int LDP = 68;   // attn row stride, u32
    constexpr int OFF_SG = 2 * STAGE;            // 256 x 68
    constexpr int OFF_SP = OFF_SG + 256 * LDG;   // 128 x 68
    constexpr int OFF_ST = OFF_SP + 128 * LDP;   // stats: 256 m + 256 s floats
    extern __shared__ uint32_t sm[];
    uint32_t sbase = (uint32_t)__cvta_generic_to_shared(sm);
    uint32_t gbase = sbase + OFF_SG * 4;
    uint32_t pbase = sbase + OFF_SP * 4;
    uint32_t* sP = sm + OFF_SP;
    float* stm = (float*)(sm + OFF_ST);
    float* sts = stm + 256;

    int tid = threadIdx.x;
    int lane = tid & 31, wid = tid >> 5;
    int wm = wid >> 1, wn = wid & 1;     // phase A: rows wm*16, cols wn*64; phase C: ch=wn
    int grp = lane >> 2, tq = lane & 3;
    int l15 = lane & 15, l16 = lane >> 4;
    int bx = blockIdx.x, zb = blockIdx.z;

    const uint32_t* Ah = Hhi + ((long long)zb * NN + bx * 128) * 128;
    const uint32_t* Alg = Hlo + ((long long)zb * NN + bx * 128) * 128;
    const uint32_t* Bh_b = Lhi + (long long)zb * NM * 128;
    const uint32_t* Bl_b = Llo + (long long)zb * NM * 128;
    const uint32_t* Gtb = Gt + (long long)zb * 256 * 512;

    // ldmatrix per-lane byte offsets
    uint32_t frA = (uint32_t)((wm * 16 + l15) * LDSR) * 4 + l16 * 16;      // within stage
    uint32_t frB = (uint32_t)((wn * 64 + l15) * LDSR) * 4 + l16 * 16;
    uint32_t frP = pbase + (uint32_t)((wm * 16 + l15) * LDP) * 4 + l16 * 16;
    uint32_t frG = gbase + (uint32_t)((wn * 128 + l15) * LDG) * 4 + l16 * 16;

    // cp.async slots: one float4 per array per thread (512 threads x 4 = 128x16 u32)
    int rr = tid >> 2, uc = (tid & 3) * 4;
    uint32_t cpo = (uint32_t)(rr * LDSR + uc) * 4;

    float o[16][4];
#pragma unroll
    for (int j = 0; j < 16; j++)
#pragma unroll
        for (int q = 0; q < 4; q++) o[j][q] = 0.f;
    float m0 = -1e30f, m1 = -1e30f, s0 = 0.f, s1 = 0.f;

    int r0 = wm * 16 + grp, r1 = r0 + 8;  // CTA-local rows

    for (int mt = 0; mt < 8; mt++) {
        const uint32_t* Bh = Bh_b + (long long)mt * 128 * 128;
        const uint32_t* Bl = Bl_b + (long long)mt * 128 * 128;

        auto issue = [&](int st, int kcp, int ch) {
            uint32_t dA = sbase + (uint32_t)st * STAGE * 4;
            cp16(dA + cpo, Ah + (long long)rr * 128 + kcp + uc);
            cp16(dA + ARR * 4 + cpo, Bh + (long long)rr * 128 + kcp + uc);
            cp16(dA + 2 * ARR * 4 + cpo, Alg + (long long)rr * 128 + kcp + uc);
            cp16(dA + 3 * ARR * 4 + cpo, Bl + (long long)rr * 128 + kcp + uc);
            int g = ch * 512 + tid;            // 4096 float4 over 8 chunks
            int gr = g >> 4, gc = (g & 15) * 4;
            cp16(gbase + (uint32_t)(gr * LDG + gc) * 4, Gtb + (long long)gr * 512 + mt * 64 + gc);
            asm volatile("cp.async.commit_group;");
        };

        float c[8][4];
#pragma unroll
        for (int j = 0; j < 8; j++)
#pragma unroll
            for (int q = 0; q < 4; q++) c[j][q] = 0.f;

        // ---- phase A: scores (cp.async double-buffered, ldmatrix frags) ----
        issue(0, 0, 0);
        asm volatile("cp.async.wait_group 0;");
        __syncthreads();
        for (int t = 0; t < 8; t++) {
            if (t + 1 < 8) issue((t + 1) & 1, (t + 1) * 16, t + 1);
            uint32_t sb = sbase + (uint32_t)(t & 1) * STAGE * 4;
            uint32_t sbA = sb + frA;
            uint32_t sbAl = sb + 2 * ARR * 4 + frA;
            uint32_t sbB = sb + ARR * 4 + frB;
            uint32_t sbBl = sb + 3 * ARR * 4 + frB;
#pragma unroll
            for (int ks = 0; ks < 2; ks++) {
                uint32_t a[4], al[4];
                ldsm_x4(a[0], a[1], a[2], a[3], sbA + ks * 32);
                ldsm_x4(al[0], al[1], al[2], al[3], sbAl + ks * 32);
#pragma unroll
                for (int jj = 0; jj < 4; jj++) {
                    uint32_t h0, h1, h2, h3, g0, g1, g2, g3;
                    ldsm_x4(h0, h1, h2, h3, sbB + jj * 1280 + ks * 32);
                    ldsm_x4(g0, g1, g2, g3, sbBl + jj * 1280 + ks * 32);
                    uint32_t b0[2] = {h0, h2}, b1[2] = {h1, h3};
                    uint32_t e0[2] = {g0, g2}, e1[2] = {g1, g3};
                    MMA16B(c[2 * jj], al, b0);
                    MMA16B(c[2 * jj], a, e0);
                    MMA16B(c[2 * jj], a, b0);
                    MMA16B(c[2 * jj + 1], al, b1);
                    MMA16B(c[2 * jj + 1], a, e1);
                    MMA16B(c[2 * jj + 1], a, b1);
                }
            }
            if (t + 1 < 8) asm volatile("cp.async.wait_group 0;");
            __syncthreads();
        }

        // ---- phase B: online softmax with cross-warp (wn) stats exchange ----
        float mx0 = -1e30f, mx1 = -1e30f;
#pragma unroll
        for (int j = 0; j < 8; j++) {
            mx0 = fmaxf(mx0, fmaxf(c[j][0], c[j][1]));
            mx1 = fmaxf(mx1, fmaxf(c[j][2], c[j][3]));
        }
        mx0 = fmaxf(mx0, __shfl_xor_sync(0xffffffffu, mx0, 1));
        mx0 = fmaxf(mx0, __shfl_xor_sync(0xffffffffu, mx0, 2));
        mx1 = fmaxf(mx1, __shfl_xor_sync(0xffffffffu, mx1, 1));
        mx1 = fmaxf(mx1, __shfl_xor_sync(0xffffffffu, mx1, 2));
        if (tq == 0) {
            stm[r0 * 2 + wn] = mx0;
            stm[r1 * 2 + wn] = mx1;
        }
        __syncthreads();
        float gm0 = fmaxf(stm[r0 * 2], stm[r0 * 2 + 1]);
        float gm1 = fmaxf(stm[r1 * 2], stm[r1 * 2 + 1]);
        float nm0 = fmaxf(m0, gm0), nm1 = fmaxf(m1, gm1);
        float sc0 = __expf(m0 - nm0), sc1 = __expf(m1 - nm1);
        m0 = nm0; m1 = nm1;
        s0 *= sc0; s1 *= sc1;
#pragma unroll
        for (int j = 0; j < 16; j++) {
            o[j][0] *= sc0; o[j][1] *= sc0;
            o[j][2] *= sc1; o[j][3] *= sc1;
        }
        float ps0 = 0.f, ps1 = 0.f;
#pragma unroll
        for (int j = 0; j < 8; j++) {
            c[j][0] = __expf(c[j][0] - m0);
            c[j][1] = __expf(c[j][1] - m0);
            c[j][2] = __expf(c[j][2] - m1);
            c[j][3] = __expf(c[j][3] - m1);
            ps0 += c[j][0] + c[j][1];
            ps1 += c[j][2] + c[j][3];
        }
        ps0 += __shfl_xor_sync(0xffffffffu, ps0, 1);
        ps0 += __shfl_xor_sync(0xffffffffu, ps0, 2);
        ps1 += __shfl_xor_sync(0xffffffffu, ps1, 1);
        ps1 += __shfl_xor_sync(0xffffffffu, ps1, 2);
        if (tq == 0) {
            sts[r0 * 2 + wn] = ps0;
            sts[r1 * 2 + wn] = ps1;
        }
        // pack exp'd attn -> smem fp16 (u32 col = wn*32 + j*4 + tq; conflict-free)
#pragma unroll
        for (int j = 0; j < 8; j++) {
            sP[r0 * LDP + wn * 32 + j * 4 + tq] = pack_hf(c[j][0], c[j][1]);
            sP[r1 * LDP + wn * 32 + j * 4 + tq] = pack_hf(c[j][2], c[j][3]);
        }
        __syncthreads();
        s0 += sts[r0 * 2] + sts[r0 * 2 + 1];
        s1 += sts[r1 * 2] + sts[r1 * 2 + 1];

        // ---- phase C: o += attn @ GT (A from attn smem, B from sG; fp16 MMA) ----
#pragma unroll
        for (int kt = 0; kt < 8; kt++) {
            uint32_t a[4];
            ldsm_x4(a[0], a[1], a[2], a[3], frP + kt * 32);
#pragma unroll
            for (int jj = 0; jj < 8; jj++) {
                uint32_t h0, h1, h2, h3;
                ldsm_x4(h0, h1, h2, h3, frG + jj * (16 * LDG * 4) + kt * 32);
                uint32_t b0[2] = {h0, h2}, b1[2] = {h1, h3};
                MMA16H(o[2 * jj], a, b0);
                MMA16H(o[2 * jj + 1], a, b1);
            }
        }
        __syncthreads();  // stages/sG/attn stable before next tile's copies
    }

    // ---- epilogue: normalize, residual, store ----
    float inv0 = 1.0f / s0, inv1 = 1.0f / s1;
    int grow = bx * 128 + r0;
    float* ob = out + ((long long)zb * NN + grow) * ND;
    const float* pb = p + ((long long)zb * NN + grow) * ND;
#pragma unroll
    for (int j = 0; j < 16; j++) {
        int col = wn * 128 + j * 8 + 2 * tq;
        float2 v0 = make_float2(o[j][0] * inv0 + pb[col], o[j][1] * inv0 + pb[col + 1]);
        float2 v1 = make_float2(o[j][2] * inv1 + pb[8 * ND + col],
                                o[j][3] * inv1 + pb[8 * ND + col + 1]);
        *(float2*)(ob + col) = v0;
        *(float2*)(ob + 8 * ND + col) = v1;
    }
}

// ---------------- launch ----------------
extern "C" void kernel_launch(void* const* d_in, const int* in_sizes, int n_in,
                              void* d_out, int out_size) {
    const float* p  = (const float*)d_in[0];
    const float* r  = (const float*)d_in[1];
    // d_in[2] = batch ids (int64) — unused (implied by layout)
    const float* Wh = (const float*)d_in[3];
    const float* bh = (const float*)d_in[4];
    const float* Wl = (const float*)d_in[5];
    const float* bl = (const float*)d_in[6];
    const float* Wg = (const float*)d_in[7];
    const float* bg = (const float*)d_in[8];
    float* out = (float*)d_out;
    (void)in_sizes; (void)n_in; (void)out_size;

    float* s = nullptr;
    cudaGetSymbolAddress((void**)&s, g_scratch);
    float* WhT = s + OFF_WHT;
    float* WlT = s + OFF_WLT;
    float* BLG = s + OFF_BLG;
    uint32_t* Hhi = (uint32_t*)(s + OFF_HHI);
    uint32_t* Hlo = (uint32_t*)(s + OFF_HLO);
    uint32_t* Lhi = (uint32_t*)(s + OFF_LHI);
    uint32_t* Llo = (uint32_t*)(s + OFF_LLO);
    float* G   = s + OFF_G;
    __half* GTh = (__half*)(s + OFF_GT);

    const int SMEM_TF32 = 4 * 128 * 36 * 4;  // 73728
    // stages 81920 + sG 69632 + attn 34816 + stats 2048
    const int SMEM_FUSED = (2 * 4 * 128 * 20 + 256 * 68 + 128 * 68 + 512) * 4;  // 188416
    cudaFuncSetAttribute(gemm_tt<true, 1>,
                         cudaFuncAttributeMaxDynamicSharedMemorySize, SMEM_TF32);
    cudaFuncSetAttribute(gemm_tt<true, 2>,
                         cudaFuncAttributeMaxDynamicSharedMemorySize, SMEM_TF32);
    cudaFuncSetAttribute(fused_attn,
                         cudaFuncAttributeMaxDynamicSharedMemorySize, SMEM_FUSED);

    // 0. transpose weights; concat biases
    transpose_w_k<<<256, 256>>>(Wh, Wl, Wg, bl, bg, WhT, WlT, WlT + (size_t)ND * ND, BLG);

    // 1. H = p @ Wh + bh  -> packed bf16 hi/lo pairs
    gemm_tt<true, 1><<<dim3(NB * NN / 128, ND / 128, 1), 256, SMEM_TF32>>>(
        p, WhT, bh, Hhi, Hlo, nullptr, ND, ND);

    // 2+3. [L | G] = r @ [Wl | Wg] + [bl | bg]  (L packed bf16, G fp32)
    gemm_tt<true, 2><<<dim3(NB * NM / 128, 2 * ND / 128, 1), 256, SMEM_TF32>>>(
        r, WlT, BLG, Lhi, Llo, G, ND, 2 * ND);

    // 4. GT[b][d][m] fp16
    transpose_g_k<<<dim3(NM / 32, ND / 32, NB), dim3(32, 8)>>>(G, GTh);

    // 5. fused: out = p + softmax(H L^T) @ G   (512 threads, 16 warps)
    fused_attn<<<dim3(NN / 128, 1, NB), 512, SMEM_FUSED>>>(
        Hhi, Hlo, Lhi, Llo, (const uint32_t*)GTh, p, out);
}